// round 6
// baseline (speedup 1.0000x reference)
#include <cuda_runtime.h>
#include <cuda_fp16.h>
#include <cuda_bf16.h>

// ---------------------------------------------------------------------------
// MultiResImplicitFeature R6: single-pass (back to R2 structure), plus
// shared-memory row assembly so output stores are fully coalesced
// (store wavefronts drop 14/pt -> 1.75/pt). No sort, no staging.
// Grids: flat channel-last fp16 (one corner = 16B = one LDG.128).
// ---------------------------------------------------------------------------

static constexpr int RES0 = 16, RES1 = 32, RES2 = 64, RES3 = 128;
static constexpr int S0 = RES0*RES0*RES0;
static constexpr int S1 = RES1*RES1*RES1;
static constexpr int S2 = RES2*RES2*RES2;
static constexpr int S3 = RES3*RES3*RES3;
static constexpr long long OFF0 = 0;
static constexpr long long OFF1 = (long long)S0*8;
static constexpr long long OFF2 = OFF1 + (long long)S1*8;
static constexpr long long OFF3 = OFF2 + (long long)S2*8;
static constexpr long long GTOTAL = OFF3 + (long long)S3*8;

__device__ __align__(256) __half g_grids[GTOTAL];

// Transpose [8, S] fp32 channel-major -> [S, 8] fp16 channel-last.
__global__ void transpose_cl_h_kernel(const float* __restrict__ in,
                                      __half* __restrict__ out, int S) {
    int i = blockIdx.x * blockDim.x + threadIdx.x;
    if (i >= S) return;
    __half v[8];
#pragma unroll
    for (int c = 0; c < 8; c++) v[c] = __float2half(__ldcs(in + (long long)c * S + i));
    *reinterpret_cast<uint4*>(out + (long long)i * 8) =
        *reinterpret_cast<const uint4*>(v);
}

template <int R>
__device__ __forceinline__ void trilerp8h(const __half* __restrict__ g,
                                          float px, float py, float pz,
                                          float* __restrict__ acc) {
    const float scale = 0.5f * (float)(R - 1);
    float cx = (px + 1.0f) * scale;
    float cy = (py + 1.0f) * scale;
    float cz = (pz + 1.0f) * scale;
    float fx = floorf(cx), fy = floorf(cy), fz = floorf(cz);
    int x0 = (int)fx; x0 = max(0, min(x0, R - 1));
    int y0 = (int)fy; y0 = max(0, min(y0, R - 1));
    int z0 = (int)fz; z0 = max(0, min(z0, R - 1));
    int x1 = min(x0 + 1, R - 1);
    int y1 = min(y0 + 1, R - 1);
    int z1 = min(z0 + 1, R - 1);
    float wx = cx - fx, wy = cy - fy, wz = cz - fz;

    float wxs[2] = {1.0f - wx, wx};
    float wys[2] = {1.0f - wy, wy};
    float wzs[2] = {1.0f - wz, wz};
    int xs[2] = {x0, x1};
    int ys[2] = {y0, y1};
    int zs[2] = {z0, z1};

#pragma unroll
    for (int dz = 0; dz < 2; dz++) {
#pragma unroll
        for (int dy = 0; dy < 2; dy++) {
            long long rowbase = ((long long)zs[dz] * R + ys[dy]) * R;
#pragma unroll
            for (int dx = 0; dx < 2; dx++) {
                long long idx = (rowbase + xs[dx]) << 3;
                uint4 v = __ldg(reinterpret_cast<const uint4*>(g + idx));
                float w = wzs[dz] * wys[dy] * wxs[dx];
                float2 f0 = __half22float2(*reinterpret_cast<__half2*>(&v.x));
                float2 f1 = __half22float2(*reinterpret_cast<__half2*>(&v.y));
                float2 f2 = __half22float2(*reinterpret_cast<__half2*>(&v.z));
                float2 f3 = __half22float2(*reinterpret_cast<__half2*>(&v.w));
                acc[0] = fmaf(w, f0.x, acc[0]);
                acc[1] = fmaf(w, f0.y, acc[1]);
                acc[2] = fmaf(w, f1.x, acc[2]);
                acc[3] = fmaf(w, f1.y, acc[3]);
                acc[4] = fmaf(w, f2.x, acc[4]);
                acc[5] = fmaf(w, f2.y, acc[5]);
                acc[6] = fmaf(w, f3.x, acc[6]);
                acc[7] = fmaf(w, f3.y, acc[7]);
            }
        }
    }
}

static constexpr int WB = 128;     // points per block
static constexpr int RSTRIDE = 57; // padded row stride (floats); 57 odd -> conflict-free

__global__ void __launch_bounds__(WB)
mrif_main_kernel(const float* __restrict__ x, float* __restrict__ out, int n) {
    __shared__ float s[WB * RSTRIDE];      // 29184 B row staging
    __shared__ float sx[WB * 3 + 4];       // block's coords

    int base = blockIdx.x * WB;
    int t = threadIdx.x;
    int valid = min(WB, n - base);

    // Coalesced load of this block's x slice (valid*3 floats).
    {
        const float* xin = x + (long long)base * 3;
        int tot = valid * 3;
        for (int w = t; w < tot; w += WB) sx[w] = __ldg(xin + w);
    }
    __syncthreads();

    if (t < valid) {
        float px = sx[t * 3 + 0];
        float py = sx[t * 3 + 1];
        float pz = sx[t * 3 + 2];

        float* row = s + t * RSTRIDE;

        const float HPI = 1.57079632679489662f;
        float p[3] = {px, py, pz};
#pragma unroll
        for (int l = 0; l < 4; l++) {
#pragma unroll
            for (int d = 0; d < 3; d++) {
                float sv, cv;
                __sincosf(HPI * (float)(l + 1) * p[d], &sv, &cv);
                row[l * 3 + d] = sv;
                row[12 + l * 3 + d] = cv;
            }
        }

        float f[32];
#pragma unroll
        for (int c = 0; c < 32; c++) f[c] = 0.0f;
        trilerp8h<RES0>(g_grids + OFF0, px, py, pz, f + 0);
        trilerp8h<RES1>(g_grids + OFF1, px, py, pz, f + 8);
        trilerp8h<RES2>(g_grids + OFF2, px, py, pz, f + 16);
        trilerp8h<RES3>(g_grids + OFF3, px, py, pz, f + 24);
#pragma unroll
        for (int c = 0; c < 32; c++) row[24 + c] = f[c];
    }
    __syncthreads();

    // Coalesced flush: valid*56 contiguous floats, 128B-line aligned stores.
    int total = valid * 56;
    float* obase = out + (long long)base * 56;
    for (int w = t * 4; w < total; w += WB * 4) {
        int r = w / 56;            // 4-word group never crosses a row (56 % 4 == 0)
        int c = w - r * 56;
        const float* sp = s + r * RSTRIDE + c;
        __stcs(reinterpret_cast<float4*>(obase + w),
               make_float4(sp[0], sp[1], sp[2], sp[3]));
    }
}

extern "C" void kernel_launch(void* const* d_in, const int* in_sizes, int n_in,
                              void* d_out, int out_size) {
    const float* x  = (const float*)d_in[0];
    const float* g0 = (const float*)d_in[1];
    const float* g1 = (const float*)d_in[2];
    const float* g2 = (const float*)d_in[3];
    const float* g3 = (const float*)d_in[4];
    float* out = (float*)d_out;

    int n = in_sizes[0] / 3;

    __half* gbase = nullptr;
    cudaGetSymbolAddress((void**)&gbase, g_grids);

    const int TT = 256;
    transpose_cl_h_kernel<<<(S0 + TT - 1) / TT, TT>>>(g0, gbase + OFF0, S0);
    transpose_cl_h_kernel<<<(S1 + TT - 1) / TT, TT>>>(g1, gbase + OFF1, S1);
    transpose_cl_h_kernel<<<(S2 + TT - 1) / TT, TT>>>(g2, gbase + OFF2, S2);
    transpose_cl_h_kernel<<<(S3 + TT - 1) / TT, TT>>>(g3, gbase + OFF3, S3);

    mrif_main_kernel<<<(n + WB - 1) / WB, WB>>>(x, out, n);
}

// round 7
// speedup vs baseline: 2.1367x; 2.1367x over previous
#include <cuda_runtime.h>
#include <cuda_fp16.h>
#include <cuda_bf16.h>
#include <cstdint>

// ---------------------------------------------------------------------------
// MultiResImplicitFeature R7: R2 structure + 256-bit memory instructions.
//  - grids stored as pair-duplicated fp16 channel-last entries:
//      entry(z,y,x) = [8ch of voxel x | 8ch of voxel min(x+1,R-1)] = 32 B
//    -> one trilerp = 4 x ld.global.v8 (one per (z,y) corner)
//  - output row (224 B, 32B-aligned) written with 7 x st.global.cs.v8.f32
//  - no smem staging, no block barriers: keep R2's latency hiding.
// ---------------------------------------------------------------------------

static constexpr int RES0 = 16, RES1 = 32, RES2 = 64, RES3 = 128;
static constexpr int S0 = RES0*RES0*RES0;
static constexpr int S1 = RES1*RES1*RES1;
static constexpr int S2 = RES2*RES2*RES2;
static constexpr int S3 = RES3*RES3*RES3;
// u32 units; 8 u32 (32 B) per entry, S entries per grid
static constexpr long long OFF0 = 0;
static constexpr long long OFF1 = (long long)S0*8;
static constexpr long long OFF2 = OFF1 + (long long)S1*8;
static constexpr long long OFF3 = OFF2 + (long long)S2*8;
static constexpr long long GTOTAL = OFF3 + (long long)S3*8;   // 19,169,280 u32 = 76.7 MB

__device__ __align__(256) uint32_t g_grids[GTOTAL];

// 256-bit load: 8 x b32 from a 32B-aligned address.
__device__ __forceinline__ void ldg256(const uint32_t* p, uint32_t r[8]) {
    asm volatile("ld.global.v8.f32 {%0,%1,%2,%3,%4,%5,%6,%7}, [%8];"
                 : "=r"(r[0]), "=r"(r[1]), "=r"(r[2]), "=r"(r[3]),
                   "=r"(r[4]), "=r"(r[5]), "=r"(r[6]), "=r"(r[7])
                 : "l"(p));
}

// 256-bit streaming store: 8 floats to a 32B-aligned address.
__device__ __forceinline__ void stg256cs(float* p, const float* v) {
    asm volatile("st.global.cs.v8.f32 [%0], {%1,%2,%3,%4,%5,%6,%7,%8};"
                 :: "l"(p), "f"(v[0]), "f"(v[1]), "f"(v[2]), "f"(v[3]),
                    "f"(v[4]), "f"(v[5]), "f"(v[6]), "f"(v[7])
                 : "memory");
}

// Build pair-duplicated fp16 channel-last entries from [8,S] fp32 input.
template <int R>
__global__ void transpose_pair_h_kernel(const float* __restrict__ in) {
    constexpr int S = R * R * R;
    int i = blockIdx.x * blockDim.x + threadIdx.x;
    if (i >= S) return;
    int x = i & (R - 1);
    int i2 = (x < R - 1) ? i + 1 : i;   // clamped x+1 neighbor

    uint32_t* out;
    if (R == RES0) out = g_grids + OFF0;
    else if (R == RES1) out = g_grids + OFF1;
    else if (R == RES2) out = g_grids + OFF2;
    else out = g_grids + OFF3;

    __half h[16];
#pragma unroll
    for (int c = 0; c < 8; c++) {
        h[c]     = __float2half(__ldcs(in + (long long)c * S + i));
        h[8 + c] = __float2half(__ldcs(in + (long long)c * S + i2));
    }
    uint4* dst = reinterpret_cast<uint4*>(out + (long long)i * 8);
    const uint4* src = reinterpret_cast<const uint4*>(h);
    dst[0] = src[0];
    dst[1] = src[1];
}

template <int R>
__device__ __forceinline__ void trilerp8p(const uint32_t* __restrict__ g,
                                          float px, float py, float pz,
                                          float* __restrict__ acc) {
    const float scale = 0.5f * (float)(R - 1);
    float cx = (px + 1.0f) * scale;
    float cy = (py + 1.0f) * scale;
    float cz = (pz + 1.0f) * scale;
    float fx = floorf(cx), fy = floorf(cy), fz = floorf(cz);
    int x0 = (int)fx; x0 = max(0, min(x0, R - 1));
    int y0 = (int)fy; y0 = max(0, min(y0, R - 1));
    int z0 = (int)fz; z0 = max(0, min(z0, R - 1));
    int y1 = min(y0 + 1, R - 1);
    int z1 = min(z0 + 1, R - 1);
    float wx = cx - fx, wy = cy - fy, wz = cz - fz;

    float wys[2] = {1.0f - wy, wy};
    float wzs[2] = {1.0f - wz, wz};
    int ys[2] = {y0, y1};
    int zs[2] = {z0, z1};
    float wxl = 1.0f - wx;

#pragma unroll
    for (int dz = 0; dz < 2; dz++) {
#pragma unroll
        for (int dy = 0; dy < 2; dy++) {
            long long e = ((long long)zs[dz] * R + ys[dy]) * R + x0;
            uint32_t r[8];
            ldg256(g + (e << 3), r);
            float wzy = wzs[dz] * wys[dy];
            float wl = wzy * wxl;
            float wr = wzy * wx;
#pragma unroll
            for (int k = 0; k < 4; k++) {
                float2 a = __half22float2(*reinterpret_cast<__half2*>(&r[k]));
                float2 b = __half22float2(*reinterpret_cast<__half2*>(&r[4 + k]));
                acc[2*k]   = fmaf(wl, a.x, fmaf(wr, b.x, acc[2*k]));
                acc[2*k+1] = fmaf(wl, a.y, fmaf(wr, b.y, acc[2*k+1]));
            }
        }
    }
}

__global__ void __launch_bounds__(256)
mrif_main_kernel(const float* __restrict__ x, float* __restrict__ out, int n) {
    int i = blockIdx.x * blockDim.x + threadIdx.x;
    if (i >= n) return;

    float px = __ldg(x + 3LL * i + 0);
    float py = __ldg(x + 3LL * i + 1);
    float pz = __ldg(x + 3LL * i + 2);

    float row[56];

    const float HPI = 1.57079632679489662f;
    float p[3] = {px, py, pz};
#pragma unroll
    for (int l = 0; l < 4; l++) {
#pragma unroll
        for (int d = 0; d < 3; d++) {
            float sv, cv;
            __sincosf(HPI * (float)(l + 1) * p[d], &sv, &cv);
            row[l * 3 + d] = sv;
            row[12 + l * 3 + d] = cv;
        }
    }

#pragma unroll
    for (int c = 0; c < 32; c++) row[24 + c] = 0.0f;
    trilerp8p<RES0>(g_grids + OFF0, px, py, pz, row + 24);
    trilerp8p<RES1>(g_grids + OFF1, px, py, pz, row + 32);
    trilerp8p<RES2>(g_grids + OFF2, px, py, pz, row + 40);
    trilerp8p<RES3>(g_grids + OFF3, px, py, pz, row + 48);

    // 56 floats = 7 x 256-bit streaming stores (row start 224B-aligned).
    float* orow = out + (long long)i * 56;
#pragma unroll
    for (int k = 0; k < 7; k++) stg256cs(orow + 8 * k, row + 8 * k);
}

extern "C" void kernel_launch(void* const* d_in, const int* in_sizes, int n_in,
                              void* d_out, int out_size) {
    const float* x  = (const float*)d_in[0];
    const float* g0 = (const float*)d_in[1];
    const float* g1 = (const float*)d_in[2];
    const float* g2 = (const float*)d_in[3];
    const float* g3 = (const float*)d_in[4];
    float* out = (float*)d_out;

    int n = in_sizes[0] / 3;

    const int TT = 256;
    transpose_pair_h_kernel<RES0><<<(S0 + TT - 1) / TT, TT>>>(g0);
    transpose_pair_h_kernel<RES1><<<(S1 + TT - 1) / TT, TT>>>(g1);
    transpose_pair_h_kernel<RES2><<<(S2 + TT - 1) / TT, TT>>>(g2);
    transpose_pair_h_kernel<RES3><<<(S3 + TT - 1) / TT, TT>>>(g3);

    mrif_main_kernel<<<(n + 255) / 256, 256>>>(x, out, n);
}

// round 8
// speedup vs baseline: 2.1641x; 1.0128x over previous
#include <cuda_runtime.h>
#include <cuda_fp16.h>
#include <cuda_bf16.h>
#include <cstdint>

// ---------------------------------------------------------------------------
// MultiResImplicitFeature R8: R7 + fused single-launch transpose + software-
// pipelined main kernel (addresses first, loads in waves, sincos overlapped).
//  - grids: pair-duplicated fp16 channel-last entries, 32 B each:
//      entry(z,y,x) = [8ch of voxel x | 8ch of voxel min(x+1,R-1)]
//    -> one trilerp = 4 x ld.global.v8.f32
//  - output row (224 B) = 7 x st.global.cs.v8.f32
// ---------------------------------------------------------------------------

static constexpr int RES0 = 16, RES1 = 32, RES2 = 64, RES3 = 128;
static constexpr int S0 = RES0*RES0*RES0;
static constexpr int S1 = RES1*RES1*RES1;
static constexpr int S2 = RES2*RES2*RES2;
static constexpr int S3 = RES3*RES3*RES3;
static constexpr long long OFF0 = 0;
static constexpr long long OFF1 = (long long)S0*8;
static constexpr long long OFF2 = OFF1 + (long long)S1*8;
static constexpr long long OFF3 = OFF2 + (long long)S2*8;
static constexpr long long GTOTAL = OFF3 + (long long)S3*8;   // 76.7 MB

__device__ __align__(256) uint32_t g_grids[GTOTAL];

__device__ __forceinline__ void ldg256(const uint32_t* p, uint32_t r[8]) {
    asm volatile("ld.global.v8.f32 {%0,%1,%2,%3,%4,%5,%6,%7}, [%8];"
                 : "=r"(r[0]), "=r"(r[1]), "=r"(r[2]), "=r"(r[3]),
                   "=r"(r[4]), "=r"(r[5]), "=r"(r[6]), "=r"(r[7])
                 : "l"(p));
}

__device__ __forceinline__ void stg256cs(float* p, const float* v) {
    asm volatile("st.global.cs.v8.f32 [%0], {%1,%2,%3,%4,%5,%6,%7,%8};"
                 :: "l"(p), "f"(v[0]), "f"(v[1]), "f"(v[2]), "f"(v[3]),
                    "f"(v[4]), "f"(v[5]), "f"(v[6]), "f"(v[7])
                 : "memory");
}

// ---------------- fused transpose (one launch, all grids) -----------------

template <int R>
__device__ __forceinline__ void do_transpose(const float* __restrict__ in,
                                             uint32_t* __restrict__ out, int i) {
    constexpr int S = R * R * R;
    int x = i & (R - 1);
    int i2 = (x < R - 1) ? i + 1 : i;
    __half h[16];
#pragma unroll
    for (int c = 0; c < 8; c++) {
        h[c]     = __float2half(__ldcs(in + (long long)c * S + i));
        h[8 + c] = __float2half(__ldcs(in + (long long)c * S + i2));
    }
    uint4* dst = reinterpret_cast<uint4*>(out + (long long)i * 8);
    const uint4* src = reinterpret_cast<const uint4*>(h);
    dst[0] = src[0];
    dst[1] = src[1];
}

static constexpr int TTOT = S3 + S2 + S1 + S0;   // 2,396,160

__global__ void __launch_bounds__(256)
fused_transpose_kernel(const float* __restrict__ g0, const float* __restrict__ g1,
                       const float* __restrict__ g2, const float* __restrict__ g3) {
    int u = blockIdx.x * blockDim.x + threadIdx.x;
    if (u < S3) {
        do_transpose<RES3>(g3, g_grids + OFF3, u);
    } else if (u < S3 + S2) {
        do_transpose<RES2>(g2, g_grids + OFF2, u - S3);
    } else if (u < S3 + S2 + S1) {
        do_transpose<RES1>(g1, g_grids + OFF1, u - S3 - S2);
    } else if (u < TTOT) {
        do_transpose<RES0>(g0, g_grids + OFF0, u - S3 - S2 - S1);
    }
}

// ---------------- main kernel: pipelined gather ---------------------------

struct TLerp {
    const uint32_t* a[4];   // 4 (z,y)-corner entry addresses
    float wzy[4];           // corner weights (product of z,y weights)
    float wx;               // x fraction
};

template <int R>
__device__ __forceinline__ TLerp prep(const uint32_t* __restrict__ g,
                                      float px, float py, float pz) {
    const float scale = 0.5f * (float)(R - 1);
    float cx = (px + 1.0f) * scale;
    float cy = (py + 1.0f) * scale;
    float cz = (pz + 1.0f) * scale;
    float fx = floorf(cx), fy = floorf(cy), fz = floorf(cz);
    int x0 = (int)fx; x0 = max(0, min(x0, R - 1));
    int y0 = (int)fy; y0 = max(0, min(y0, R - 1));
    int z0 = (int)fz; z0 = max(0, min(z0, R - 1));
    int y1 = min(y0 + 1, R - 1);
    int z1 = min(z0 + 1, R - 1);
    float wx = cx - fx, wy = cy - fy, wz = cz - fz;

    TLerp t;
    t.wx = wx;
    long long b00 = ((long long)z0 * R + y0) * R + x0;
    long long b01 = ((long long)z0 * R + y1) * R + x0;
    long long b10 = ((long long)z1 * R + y0) * R + x0;
    long long b11 = ((long long)z1 * R + y1) * R + x0;
    t.a[0] = g + (b00 << 3);
    t.a[1] = g + (b01 << 3);
    t.a[2] = g + (b10 << 3);
    t.a[3] = g + (b11 << 3);
    t.wzy[0] = (1.0f - wz) * (1.0f - wy);
    t.wzy[1] = (1.0f - wz) * wy;
    t.wzy[2] = wz * (1.0f - wy);
    t.wzy[3] = wz * wy;
    return t;
}

__device__ __forceinline__ void load4(const TLerp& t, uint32_t r[4][8]) {
#pragma unroll
    for (int c = 0; c < 4; c++) ldg256(t.a[c], r[c]);
}

__device__ __forceinline__ void accum4(const TLerp& t, const uint32_t r[4][8],
                                       float* __restrict__ acc) {
    float wxl = 1.0f - t.wx;
    float wxr = t.wx;
#pragma unroll
    for (int c = 0; c < 4; c++) {
        float wl = t.wzy[c] * wxl;
        float wr = t.wzy[c] * wxr;
#pragma unroll
        for (int k = 0; k < 4; k++) {
            float2 a = __half22float2(*reinterpret_cast<const __half2*>(&r[c][k]));
            float2 b = __half22float2(*reinterpret_cast<const __half2*>(&r[c][4 + k]));
            acc[2*k]   = fmaf(wl, a.x, fmaf(wr, b.x, acc[2*k]));
            acc[2*k+1] = fmaf(wl, a.y, fmaf(wr, b.y, acc[2*k+1]));
        }
    }
}

__global__ void __launch_bounds__(256)
mrif_main_kernel(const float* __restrict__ x, float* __restrict__ out, int n) {
    int i = blockIdx.x * blockDim.x + threadIdx.x;
    if (i >= n) return;

    float px = __ldg(x + 3LL * i + 0);
    float py = __ldg(x + 3LL * i + 1);
    float pz = __ldg(x + 3LL * i + 2);

    // Phase 1: all gather addresses (pure ALU, no loads yet).
    TLerp t0 = prep<RES0>(g_grids + OFF0, px, py, pz);
    TLerp t1 = prep<RES1>(g_grids + OFF1, px, py, pz);
    TLerp t2 = prep<RES2>(g_grids + OFF2, px, py, pz);
    TLerp t3 = prep<RES3>(g_grids + OFF3, px, py, pz);

    // Phase 2: first load wave (grids 0,1).
    uint32_t r0[4][8], r1[4][8];
    load4(t0, r0);
    load4(t1, r1);

    // Phase 3: sincos overlapped with loads in flight.
    float row[56];
    {
        const float HPI = 1.57079632679489662f;
        float p[3] = {px, py, pz};
#pragma unroll
        for (int l = 0; l < 4; l++) {
#pragma unroll
            for (int d = 0; d < 3; d++) {
                float sv, cv;
                __sincosf(HPI * (float)(l + 1) * p[d], &sv, &cv);
                row[l * 3 + d] = sv;
                row[12 + l * 3 + d] = cv;
            }
        }
    }
#pragma unroll
    for (int c = 0; c < 32; c++) row[24 + c] = 0.0f;

    // Phase 4: second load wave interleaved with consumption.
    uint32_t r2[4][8];
    load4(t2, r2);
    accum4(t0, r0, row + 24);
    uint32_t r3[4][8];
    load4(t3, r3);
    accum4(t1, r1, row + 32);
    accum4(t2, r2, row + 40);
    accum4(t3, r3, row + 48);

    // 7 x 256-bit streaming stores.
    float* orow = out + (long long)i * 56;
#pragma unroll
    for (int k = 0; k < 7; k++) stg256cs(orow + 8 * k, row + 8 * k);
}

extern "C" void kernel_launch(void* const* d_in, const int* in_sizes, int n_in,
                              void* d_out, int out_size) {
    const float* x  = (const float*)d_in[0];
    const float* g0 = (const float*)d_in[1];
    const float* g1 = (const float*)d_in[2];
    const float* g2 = (const float*)d_in[3];
    const float* g3 = (const float*)d_in[4];
    float* out = (float*)d_out;

    int n = in_sizes[0] / 3;

    const int TT = 256;
    fused_transpose_kernel<<<(TTOT + TT - 1) / TT, TT>>>(g0, g1, g2, g3);
    mrif_main_kernel<<<(n + 255) / 256, 256>>>(x, out, n);
}